// round 11
// baseline (speedup 1.0000x reference)
#include <cuda_runtime.h>
#include <cstdint>

#define kB   4
#define kDEC 256
#define kENC 1024
#define kHID 512
#define kU   128

#define QSPLIT 8
#define KSPLIT 8
#define CSPLIT 8

#define QP_STRIDE (1024 * 128)   // one qproj part
#define KP_STRIDE (4096 * 128)   // one kproj part
#define CP_STRIDE (256 * 512)    // one ctx part

// score smem: 512(qs) + 128(scl) + 16(red) + 2*64*132(ks dbl buf) floats
#define SCORE_SMEM_FLOATS (512 + 128 + 16 + 2 * 64 * 132)
#define SCORE_SMEM_BYTES  (SCORE_SMEM_FLOATS * 4)

__device__ float g_qp[QSPLIT * QP_STRIDE];
__device__ float g_kp[KSPLIT * KP_STRIDE];
__device__ float g_q[kB * kDEC * kU];
__device__ float g_k[kB * kENC * kU];
__device__ float g_cp[kB * CSPLIT * CP_STRIDE];

__device__ __forceinline__ float tanh_approx(float x) {
    float y;
    asm("tanh.approx.f32 %0, %1;" : "=f"(y) : "f"(x));
    return y;
}
__device__ __forceinline__ unsigned long long pack2(float x, float y) {
    unsigned long long r;
    asm("mov.b64 %0, {%1, %2};" : "=l"(r) : "f"(x), "f"(y));
    return r;
}
__device__ __forceinline__ float2 unpack2(unsigned long long v) {
    float2 f;
    asm("mov.b64 {%0, %1}, %2;" : "=f"(f.x), "=f"(f.y) : "l"(v));
    return f;
}
__device__ __forceinline__ void fma2(unsigned long long& d,
                                     unsigned long long a, unsigned long long b) {
    asm("fma.rn.f32x2 %0, %1, %2, %0;" : "+l"(d) : "l"(a), "l"(b));
}
__device__ __forceinline__ uint32_t smem_u32(const void* p) {
    return (uint32_t)__cvta_generic_to_shared(p);
}
__device__ __forceinline__ void cp_async16(uint32_t saddr, const void* gptr) {
    asm volatile("cp.async.cg.shared.global [%0], [%1], 16;"
                 :: "r"(saddr), "l"(gptr) : "memory");
}
__device__ __forceinline__ void cp_commit() {
    asm volatile("cp.async.commit_group;" ::: "memory");
}
template <int N>
__device__ __forceinline__ void cp_wait() {
    asm volatile("cp.async.wait_group %0;" :: "n"(N) : "memory");
}

// ---------------------------------------------------------------------------
// Combined q/k projection, balanced K-split (all blocks: 128x128x64).
// ---------------------------------------------------------------------------
__global__ __launch_bounds__(256, 2) void proj_kernel(
    const float* __restrict__ query, const float* __restrict__ W1,
    const float* __restrict__ value, const float* __restrict__ W2)
{
    __shared__ float As[16][132];
    __shared__ float Bs[16][128];

    const int z = blockIdx.x;
    const float *Ab, *Bb;
    float* Cb;
    int kbeg, m0;
    const int Klocal = 64;
    if (z < 64) {
        int part = z >> 3, mt = z & 7;
        Ab = query; Bb = W1; Cb = g_qp + (long)part * QP_STRIDE;
        kbeg = part * Klocal; m0 = mt * 128;
    } else {
        int t = z - 64;
        int part = t >> 5, mt = t & 31;
        Ab = value; Bb = W2; Cb = g_kp + (long)part * KP_STRIDE;
        kbeg = part * Klocal; m0 = mt * 128;
    }
    const int K = 512, N = 128;

    const int tid = threadIdx.x;
    const int tx = tid & 15, ty = tid >> 4;
    const int am = tid >> 1,  ak = (tid & 1) * 8;
    const int bk = tid >> 4,  bn = (tid & 15) * 8;

    const float* Aptr = Ab + (long)(m0 + am) * K + kbeg + ak;
    const float* Bptr = Bb + (long)(kbeg + bk) * N + bn;

    unsigned long long acc[8][4];
#pragma unroll
    for (int i = 0; i < 8; i++)
#pragma unroll
        for (int j = 0; j < 4; j++) acc[i][j] = 0ull;

    float4 a0 = *(const float4*)(Aptr);
    float4 a1 = *(const float4*)(Aptr + 4);
    float4 b0 = *(const float4*)(Bptr);
    float4 b1 = *(const float4*)(Bptr + 4);

    for (int kt = 0; kt < Klocal; kt += 16) {
        As[ak + 0][am] = a0.x; As[ak + 1][am] = a0.y;
        As[ak + 2][am] = a0.z; As[ak + 3][am] = a0.w;
        As[ak + 4][am] = a1.x; As[ak + 5][am] = a1.y;
        As[ak + 6][am] = a1.z; As[ak + 7][am] = a1.w;
        *(float4*)&Bs[bk][bn]     = b0;
        *(float4*)&Bs[bk][bn + 4] = b1;
        __syncthreads();

        int kn = (kt + 16 < Klocal) ? kt + 16 : 0;
        a0 = *(const float4*)(Aptr + kn);
        a1 = *(const float4*)(Aptr + kn + 4);
        b0 = *(const float4*)(Bptr + (long)kn * N);
        b1 = *(const float4*)(Bptr + (long)kn * N + 4);

#pragma unroll
        for (int kk = 0; kk < 16; kk++) {
            float4 av0 = *(const float4*)&As[kk][ty * 8];
            float4 av1 = *(const float4*)&As[kk][ty * 8 + 4];
            float4 bv0 = *(const float4*)&Bs[kk][tx * 8];
            float4 bv1 = *(const float4*)&Bs[kk][tx * 8 + 4];
            unsigned long long bp0 = pack2(bv0.x, bv0.y);
            unsigned long long bp1 = pack2(bv0.z, bv0.w);
            unsigned long long bp2 = pack2(bv1.x, bv1.y);
            unsigned long long bp3 = pack2(bv1.z, bv1.w);
            float av[8] = {av0.x, av0.y, av0.z, av0.w, av1.x, av1.y, av1.z, av1.w};
#pragma unroll
            for (int i = 0; i < 8; i++) {
                unsigned long long ap = pack2(av[i], av[i]);
                fma2(acc[i][0], ap, bp0);
                fma2(acc[i][1], ap, bp1);
                fma2(acc[i][2], ap, bp2);
                fma2(acc[i][3], ap, bp3);
            }
        }
        __syncthreads();
    }

#pragma unroll
    for (int i = 0; i < 8; i++) {
        float2 c0 = unpack2(acc[i][0]), c1 = unpack2(acc[i][1]);
        float2 c2 = unpack2(acc[i][2]), c3 = unpack2(acc[i][3]);
        float* crow = Cb + (long)(m0 + ty * 8 + i) * N + tx * 8;
        *(float4*)crow       = make_float4(c0.x, c0.y, c1.x, c1.y);
        *(float4*)(crow + 4) = make_float4(c2.x, c2.y, c3.x, c3.y);
    }
}

// ---------------------------------------------------------------------------
// f32x2 GEMM, 128x128 tile, 8x8 micro, deterministic K-split (ctx GEMM).
// launch_bounds(256,2): cap regs at 128 so 2 CTAs co-reside per SM.
// ---------------------------------------------------------------------------
__global__ __launch_bounds__(256, 2) void gemm128(
    const float* __restrict__ A, const float* __restrict__ Bm, float* __restrict__ C,
    int M, int N, int K, int nsplit, long sA, long sB)
{
    __shared__ float As[16][132];
    __shared__ float Bs[16][128];

    const int z = blockIdx.z;
    const int b = z / nsplit;
    const int s = z - b * nsplit;
    const int Klocal = K / nsplit;
    const int kbeg = s * Klocal;

    const float* Ab = A + (long)b * sA;
    const float* Bb = Bm + (long)b * sB;
    float*       Cb = C + (long)z * M * N;

    const int m0 = blockIdx.y * 128;
    const int n0 = blockIdx.x * 128;

    const int tid = threadIdx.x;
    const int tx = tid & 15, ty = tid >> 4;

    const int am = tid >> 1,  ak = (tid & 1) * 8;
    const int bk = tid >> 4,  bn = (tid & 15) * 8;

    const float* Aptr = Ab + (long)(m0 + am) * K + kbeg + ak;
    const float* Bptr = Bb + (long)(kbeg + bk) * N + n0 + bn;

    unsigned long long acc[8][4];
#pragma unroll
    for (int i = 0; i < 8; i++)
#pragma unroll
        for (int j = 0; j < 4; j++) acc[i][j] = 0ull;

    float4 a0 = *(const float4*)(Aptr);
    float4 a1 = *(const float4*)(Aptr + 4);
    float4 b0 = *(const float4*)(Bptr);
    float4 b1 = *(const float4*)(Bptr + 4);

    for (int kt = 0; kt < Klocal; kt += 16) {
        As[ak + 0][am] = a0.x; As[ak + 1][am] = a0.y;
        As[ak + 2][am] = a0.z; As[ak + 3][am] = a0.w;
        As[ak + 4][am] = a1.x; As[ak + 5][am] = a1.y;
        As[ak + 6][am] = a1.z; As[ak + 7][am] = a1.w;
        *(float4*)&Bs[bk][bn]     = b0;
        *(float4*)&Bs[bk][bn + 4] = b1;
        __syncthreads();

        int kn = (kt + 16 < Klocal) ? kt + 16 : 0;
        a0 = *(const float4*)(Aptr + kn);
        a1 = *(const float4*)(Aptr + kn + 4);
        b0 = *(const float4*)(Bptr + (long)kn * N);
        b1 = *(const float4*)(Bptr + (long)kn * N + 4);

#pragma unroll
        for (int kk = 0; kk < 16; kk++) {
            float4 av0 = *(const float4*)&As[kk][ty * 8];
            float4 av1 = *(const float4*)&As[kk][ty * 8 + 4];
            float4 bv0 = *(const float4*)&Bs[kk][tx * 8];
            float4 bv1 = *(const float4*)&Bs[kk][tx * 8 + 4];
            unsigned long long bp0 = pack2(bv0.x, bv0.y);
            unsigned long long bp1 = pack2(bv0.z, bv0.w);
            unsigned long long bp2 = pack2(bv1.x, bv1.y);
            unsigned long long bp3 = pack2(bv1.z, bv1.w);
            float av[8] = {av0.x, av0.y, av0.z, av0.w, av1.x, av1.y, av1.z, av1.w};
#pragma unroll
            for (int i = 0; i < 8; i++) {
                unsigned long long ap = pack2(av[i], av[i]);
                fma2(acc[i][0], ap, bp0);
                fma2(acc[i][1], ap, bp1);
                fma2(acc[i][2], ap, bp2);
                fma2(acc[i][3], ap, bp3);
            }
        }
        __syncthreads();
    }

#pragma unroll
    for (int i = 0; i < 8; i++) {
        float2 c0 = unpack2(acc[i][0]), c1 = unpack2(acc[i][1]);
        float2 c2 = unpack2(acc[i][2]), c3 = unpack2(acc[i][3]);
        float* crow = Cb + (long)(m0 + ty * 8 + i) * N + n0 + tx * 8;
        *(float4*)crow       = make_float4(c0.x, c0.y, c1.x, c1.y);
        *(float4*)(crow + 4) = make_float4(c2.x, c2.y, c3.x, c3.y);
    }
}

// ---------------------------------------------------------------------------
// Sum projection K-split parts: g_qp(8) -> g_q, g_kp(8) -> g_k.
// ---------------------------------------------------------------------------
#define QN (kB * kDEC * kU / 4)    // 32768 float4
#define KN (kB * kENC * kU / 4)    // 131072 float4
__global__ __launch_bounds__(256) void reduce_qk_kernel()
{
    int idx = blockIdx.x * 256 + threadIdx.x;
    if (idx < QN) {
        const float4* p = (const float4*)g_qp;
        float4 s = make_float4(0.f, 0.f, 0.f, 0.f);
#pragma unroll
        for (int j = 0; j < QSPLIT; j++) {
            float4 v = p[idx + j * (QP_STRIDE / 4)];
            s.x += v.x; s.y += v.y; s.z += v.z; s.w += v.w;
        }
        ((float4*)g_q)[idx] = s;
    } else {
        int i = idx - QN;
        const float4* p = (const float4*)g_kp;
        float4 s = make_float4(0.f, 0.f, 0.f, 0.f);
#pragma unroll
        for (int j = 0; j < KSPLIT; j++) {
            float4 v = p[i + j * (KP_STRIDE / 4)];
            s.x += v.x; s.y += v.y; s.z += v.z; s.w += v.w;
        }
        ((float4*)g_k)[i] = s;
    }
}

// ---------------------------------------------------------------------------
// ctx = sum of CSPLIT K-split parts per batch.
// ---------------------------------------------------------------------------
__global__ __launch_bounds__(256) void reduce_ctx_kernel(float4* __restrict__ out)
{
    const float4* p = (const float4*)g_cp;
    const int idx = blockIdx.x * 256 + threadIdx.x;
    const int slice = CP_STRIDE / 4;
    const int b = idx / slice;
    const int i = idx - b * slice;
    const float4* base = p + (long)(b * CSPLIT) * slice + i;
    float4 s = make_float4(0.f, 0.f, 0.f, 0.f);
#pragma unroll
    for (int j = 0; j < CSPLIT; j++) {
        float4 v = base[(long)j * slice];
        s.x += v.x; s.y += v.y; s.z += v.z; s.w += v.w;
    }
    out[idx] = s;
}

// ---------------------------------------------------------------------------
// FUSED additive scores + masked softmax -> wts.
// Grid 256 (b, 4 queries), 256 threads. Warp w: query q = w>>1, half = w&1.
// Each lane owns row half*32+lane of every 64-row k tile -> sc[16] local.
// cp.async double-buffered tiles; softmax = warp reduce + pair combine in smem.
// ---------------------------------------------------------------------------
__global__ __launch_bounds__(256) void score_softmax_kernel(
    const float* __restrict__ scale, const int* __restrict__ mask,
    float* __restrict__ wts)
{
    extern __shared__ float sm[];
    float* qs  = sm;                  // 4 * 128
    float* scl = qs + 4 * kU;         // 128
    float* red = scl + kU;            // 16
    float* ks0 = red + 16;            // 64 * 132
    float* ks1 = ks0 + 64 * 132;      // 64 * 132

    const int unit = blockIdx.x;      // 0..255
    const int b  = unit >> 6;
    const int q0 = (unit & 63) * 4;
    const int tid  = threadIdx.x;
    const int w    = tid >> 5;        // warp 0..7
    const int q    = w >> 1;          // query 0..3
    const int half = w & 1;           // row half
    const int lane = tid & 31;
    const int myrow = half * 32 + lane;

    const uint32_t qs_a  = smem_u32(qs);
    const uint32_t ks0_a = smem_u32(ks0);
    const uint32_t ks1_a = smem_u32(ks1);

    const int trow = tid >> 5;          // staging base row 0..7
    const int tcol = (tid & 31) * 4;    // staging col 0..124

    const float* kbase = g_k + (long)b * kENC * kU;
    const float* qsrc  = g_q + (long)(b * kDEC + q0) * kU;
    const int*   mrow  = mask + b * kENC;

    if (tid < kU) scl[tid] = scale[tid];

    // stage qs (512 floats) + tile 0 as one cp.async group
    if (tid < 128) cp_async16(qs_a + tid * 16, qsrc + tid * 4);
#pragma unroll
    for (int j = 0; j < 8; j++) {
        int r = trow + j * 8;
        cp_async16(ks0_a + (r * 132 + tcol) * 4, kbase + (long)r * kU + tcol);
    }
    cp_commit();

    const float* qr = qs + q * kU;
    float sc[16];

    for (int t = 0; t < 16; t++) {
        const float* kst = (t & 1) ? ks1 : ks0;
        const uint32_t nxt = (t & 1) ? ks0_a : ks1_a;

        if (t < 15) {
#pragma unroll
            for (int j = 0; j < 8; j++) {
                int r = trow + j * 8;
                cp_async16(nxt + (r * 132 + tcol) * 4,
                           kbase + (long)((t + 1) * 64 + r) * kU + tcol);
            }
            cp_commit();
            cp_wait<1>();
        } else {
            cp_wait<0>();
        }
        __syncthreads();

        const float* kr = kst + myrow * 132;
        float s0 = 0.f;
#pragma unroll 8
        for (int uu = 0; uu < kU; uu += 4) {
            float4 qv = *(const float4*)(qr + uu);
            float4 sv = *(const float4*)(scl + uu);
            float4 a = *(const float4*)(kr + uu);
            s0 = fmaf(sv.x, tanh_approx(qv.x + a.x), s0);
            s0 = fmaf(sv.y, tanh_approx(qv.y + a.y), s0);
            s0 = fmaf(sv.z, tanh_approx(qv.z + a.z), s0);
            s0 = fmaf(sv.w, tanh_approx(qv.w + a.w), s0);
        }
        int e0 = t * 64 + myrow;
        sc[t] = (mrow[e0] == 0) ? -1e9f : s0;
        __syncthreads();       // compute done before next prefetch overwrites
    }

    // softmax: warp reduce over 16 local scores, combine warp pair via smem
    float mx = -3.4e38f;
#pragma unroll
    for (int j = 0; j < 16; j++) mx = fmaxf(mx, sc[j]);
#pragma unroll
    for (int off = 16; off > 0; off >>= 1)
        mx = fmaxf(mx, __shfl_xor_sync(0xffffffffu, mx, off));
    if (lane == 0) red[w] = mx;
    __syncthreads();
    mx = fmaxf(red[w & ~1], red[w | 1]);

    float ssum = 0.f;
#pragma unroll
    for (int j = 0; j < 16; j++) {
        float p = __expf(sc[j] - mx);
        sc[j] = p;
        ssum += p;
    }
#pragma unroll
    for (int off = 16; off > 0; off >>= 1)
        ssum += __shfl_xor_sync(0xffffffffu, ssum, off);
    if (lane == 0) red[8 + w] = ssum;
    __syncthreads();
    ssum = red[8 + (w & ~1)] + red[8 + (w | 1)];
    const float inv = 1.0f / ssum;

    float* wrow = wts + (long)(b * kDEC + q0 + q) * kENC;
#pragma unroll
    for (int j = 0; j < 16; j++)
        wrow[j * 64 + myrow] = sc[j] * inv;
}

// ---------------------------------------------------------------------------
extern "C" void kernel_launch(void* const* d_in, const int* in_sizes, int n_in,
                              void* d_out, int out_size)
{
    const float* query = (const float*)d_in[0];
    const float* value = (const float*)d_in[1];
    const int*   mask  = (const int*)d_in[2];
    const float* W1    = (const float*)d_in[3];
    const float* W2    = (const float*)d_in[4];
    const float* scale = (const float*)d_in[5];

    float* ctx = (float*)d_out;                          // (B, DEC, HID)
    float* wts = ctx + (size_t)kB * kDEC * kHID;         // (B, DEC, ENC)

    float* cp;
    cudaGetSymbolAddress((void**)&cp, g_cp);

    cudaFuncSetAttribute(score_softmax_kernel,
        cudaFuncAttributeMaxDynamicSharedMemorySize, SCORE_SMEM_BYTES);

    // combined q+k projections, balanced split (320 blocks, 2 CTAs/SM)
    proj_kernel<<<320, 256>>>(query, W1, value, W2);

    // sum projection parts
    reduce_qk_kernel<<<(QN + KN) / 256, 256>>>();

    // fused masked scores + softmax -> weights (256 blocks, 4 queries each)
    score_softmax_kernel<<<kB * 64, 256, SCORE_SMEM_BYTES>>>(scale, mask, wts);

    // context: per-batch (256,1024)@(1024,512), split 8 -> 256 blocks, 2 CTAs/SM
    gemm128<<<dim3(4, 2, kB * CSPLIT), 256>>>(wts, value, cp, 256, 512, 1024, CSPLIT,
                                              (long)kDEC * kENC, (long)kENC * kHID);

    // sum ctx parts -> d_out
    reduce_ctx_kernel<<<(kB * CP_STRIDE / 4) / 256, 256>>>((float4*)ctx);
}

// round 12
// speedup vs baseline: 1.1830x; 1.1830x over previous
#include <cuda_runtime.h>
#include <cstdint>

#define kB   4
#define kDEC 256
#define kENC 1024
#define kHID 512
#define kU   128

#define QSPLIT 8
#define KSPLIT 8
#define CSPLIT 8

#define QP_STRIDE (1024 * 128)   // one qproj part
#define KP_STRIDE (4096 * 128)   // one kproj part
#define CP_STRIDE (256 * 512)    // one ctx part

// score smem: 1024(qs) + 128(scl) + 128*132(ks) floats = 72,192 B -> 3 CTAs/SM
#define SCORE_SMEM_FLOATS (1024 + 128 + 128*132)
#define SCORE_SMEM_BYTES  (SCORE_SMEM_FLOATS * 4)

__device__ float g_qp[QSPLIT * QP_STRIDE];
__device__ float g_kp[KSPLIT * KP_STRIDE];
__device__ float g_q[kB * kDEC * kU];
__device__ float g_k[kB * kENC * kU];
__device__ float g_cp[kB * CSPLIT * CP_STRIDE];
__device__ float g_sc[kB * kDEC * kENC];   // raw masked scores

__device__ __forceinline__ float tanh_approx(float x) {
    float y;
    asm("tanh.approx.f32 %0, %1;" : "=f"(y) : "f"(x));
    return y;
}
__device__ __forceinline__ unsigned long long pack2(float x, float y) {
    unsigned long long r;
    asm("mov.b64 %0, {%1, %2};" : "=l"(r) : "f"(x), "f"(y));
    return r;
}
__device__ __forceinline__ float2 unpack2(unsigned long long v) {
    float2 f;
    asm("mov.b64 {%0, %1}, %2;" : "=f"(f.x), "=f"(f.y) : "l"(v));
    return f;
}
__device__ __forceinline__ void fma2(unsigned long long& d,
                                     unsigned long long a, unsigned long long b) {
    asm("fma.rn.f32x2 %0, %1, %2, %0;" : "+l"(d) : "l"(a), "l"(b));
}

// ---------------------------------------------------------------------------
// Conflict-free f32x2 GEMM core. 128x128 tile, 256 threads.
// Thread (tx,ty) owns rows {ty*4+i, 64+ty*4+i} x cols {tx*4.., 64+tx*4..}.
// B LDS.128 phases are 128B-contiguous -> no bank conflicts; A broadcasts.
// ---------------------------------------------------------------------------
#define GEMM_CORE(Aptr, Bptr, Cb, Kstride, Nval, Klocal, m0, n0)               \
{                                                                              \
    const int tid = threadIdx.x;                                               \
    const int tx = tid & 15, ty = tid >> 4;                                    \
    const int am = tid >> 1,  ak = (tid & 1) * 8;                              \
    const int bk = tid >> 4,  bn = (tid & 15) * 8;                             \
    const float* Ap = (Aptr) + (long)(m0 + am) * (Kstride) + ak;               \
    const float* Bp = (Bptr) + (long)bk * (Nval) + n0 + bn;                    \
    unsigned long long acc[8][4];                                              \
    _Pragma("unroll")                                                          \
    for (int i = 0; i < 8; i++) { acc[i][0]=0; acc[i][1]=0; acc[i][2]=0; acc[i][3]=0; } \
    float4 a0 = *(const float4*)(Ap);                                          \
    float4 a1 = *(const float4*)(Ap + 4);                                      \
    float4 b0 = *(const float4*)(Bp);                                          \
    float4 b1 = *(const float4*)(Bp + 4);                                      \
    for (int kt = 0; kt < (Klocal); kt += 16) {                                \
        As[ak + 0][am] = a0.x; As[ak + 1][am] = a0.y;                          \
        As[ak + 2][am] = a0.z; As[ak + 3][am] = a0.w;                          \
        As[ak + 4][am] = a1.x; As[ak + 5][am] = a1.y;                          \
        As[ak + 6][am] = a1.z; As[ak + 7][am] = a1.w;                          \
        *(float4*)&Bs[bk][bn]     = b0;                                        \
        *(float4*)&Bs[bk][bn + 4] = b1;                                        \
        __syncthreads();                                                       \
        int kn = (kt + 16 < (Klocal)) ? kt + 16 : 0;                           \
        a0 = *(const float4*)(Ap + kn);                                        \
        a1 = *(const float4*)(Ap + kn + 4);                                    \
        b0 = *(const float4*)(Bp + (long)kn * (Nval));                         \
        b1 = *(const float4*)(Bp + (long)kn * (Nval) + 4);                     \
        _Pragma("unroll")                                                      \
        for (int kk = 0; kk < 16; kk++) {                                      \
            float4 av0 = *(const float4*)&As[kk][ty * 4];                      \
            float4 av1 = *(const float4*)&As[kk][64 + ty * 4];                 \
            float4 bv0 = *(const float4*)&Bs[kk][tx * 4];                      \
            float4 bv1 = *(const float4*)&Bs[kk][64 + tx * 4];                 \
            unsigned long long bp0 = pack2(bv0.x, bv0.y);                      \
            unsigned long long bp1 = pack2(bv0.z, bv0.w);                      \
            unsigned long long bp2 = pack2(bv1.x, bv1.y);                      \
            unsigned long long bp3 = pack2(bv1.z, bv1.w);                      \
            float av[8] = {av0.x, av0.y, av0.z, av0.w, av1.x, av1.y, av1.z, av1.w}; \
            _Pragma("unroll")                                                  \
            for (int i = 0; i < 8; i++) {                                      \
                unsigned long long ap = pack2(av[i], av[i]);                   \
                fma2(acc[i][0], ap, bp0);                                      \
                fma2(acc[i][1], ap, bp1);                                      \
                fma2(acc[i][2], ap, bp2);                                      \
                fma2(acc[i][3], ap, bp3);                                      \
            }                                                                  \
        }                                                                      \
        __syncthreads();                                                       \
    }                                                                          \
    _Pragma("unroll")                                                          \
    for (int i = 0; i < 8; i++) {                                              \
        int row = (i < 4) ? (m0 + ty * 4 + i) : (m0 + 64 + ty * 4 + i - 4);    \
        float2 c0 = unpack2(acc[i][0]), c1 = unpack2(acc[i][1]);               \
        float2 c2 = unpack2(acc[i][2]), c3 = unpack2(acc[i][3]);               \
        float* crow = (Cb) + (long)row * (Nval) + n0;                          \
        *(float4*)(crow + tx * 4)      = make_float4(c0.x, c0.y, c1.x, c1.y);  \
        *(float4*)(crow + 64 + tx * 4) = make_float4(c2.x, c2.y, c3.x, c3.y);  \
    }                                                                          \
}

// ---------------------------------------------------------------------------
// Combined q/k projection, balanced K-split (all blocks: 128x128x64).
// ---------------------------------------------------------------------------
__global__ __launch_bounds__(256, 2) void proj_kernel(
    const float* __restrict__ query, const float* __restrict__ W1,
    const float* __restrict__ value, const float* __restrict__ W2)
{
    __shared__ float As[16][132];
    __shared__ float Bs[16][128];

    const int z = blockIdx.x;
    const float *Ab, *Bb;
    float* Cb;
    int kbeg, m0;
    if (z < 64) {
        int part = z >> 3, mt = z & 7;
        Ab = query; Bb = W1; Cb = g_qp + (long)part * QP_STRIDE;
        kbeg = part * 64; m0 = mt * 128;
    } else {
        int t = z - 64;
        int part = t >> 5, mt = t & 31;
        Ab = value; Bb = W2; Cb = g_kp + (long)part * KP_STRIDE;
        kbeg = part * 64; m0 = mt * 128;
    }
    const float* Abk = Ab + kbeg;
    const float* Bbk = Bb + (long)kbeg * 128;
    GEMM_CORE(Abk, Bbk, Cb, 512, 128, 64, m0, 0)
}

// ---------------------------------------------------------------------------
// ctx partial GEMM: per (batch, split) of (256,1024)@(1024,512).
// ---------------------------------------------------------------------------
__global__ __launch_bounds__(256, 2) void gemm128(
    const float* __restrict__ A, const float* __restrict__ Bm, float* __restrict__ C,
    int M, int N, int K, int nsplit, long sA, long sB)
{
    __shared__ float As[16][132];
    __shared__ float Bs[16][128];

    const int z = blockIdx.z;
    const int b = z / nsplit;
    const int s = z - b * nsplit;
    const int Klocal = K / nsplit;
    const int kbeg = s * Klocal;

    const float* Ab = A + (long)b * sA + kbeg;
    const float* Bb = Bm + (long)b * sB + (long)kbeg * N;
    float*       Cb = C + (long)z * M * N;

    const int m0 = blockIdx.y * 128;
    const int n0 = blockIdx.x * 128;
    GEMM_CORE(Ab, Bb, Cb, K, N, Klocal, m0, n0)
}

// ---------------------------------------------------------------------------
// Sum projection K-split parts: g_qp(8) -> g_q, g_kp(8) -> g_k.
// ---------------------------------------------------------------------------
#define QN (kB * kDEC * kU / 4)    // 32768 float4
#define KN (kB * kENC * kU / 4)    // 131072 float4
__global__ __launch_bounds__(256) void reduce_qk_kernel()
{
    int idx = blockIdx.x * 256 + threadIdx.x;
    if (idx < QN) {
        const float4* p = (const float4*)g_qp;
        float4 s = make_float4(0.f, 0.f, 0.f, 0.f);
#pragma unroll
        for (int j = 0; j < QSPLIT; j++) {
            float4 v = p[idx + j * (QP_STRIDE / 4)];
            s.x += v.x; s.y += v.y; s.z += v.z; s.w += v.w;
        }
        ((float4*)g_q)[idx] = s;
    } else {
        int i = idx - QN;
        const float4* p = (const float4*)g_kp;
        float4 s = make_float4(0.f, 0.f, 0.f, 0.f);
#pragma unroll
        for (int j = 0; j < KSPLIT; j++) {
            float4 v = p[i + j * (KP_STRIDE / 4)];
            s.x += v.x; s.y += v.y; s.z += v.z; s.w += v.w;
        }
        ((float4*)g_k)[i] = s;
    }
}

// ---------------------------------------------------------------------------
// ctx = sum of CSPLIT K-split parts per batch.
// ---------------------------------------------------------------------------
__global__ __launch_bounds__(256) void reduce_ctx_kernel(float4* __restrict__ out)
{
    const float4* p = (const float4*)g_cp;
    const int idx = blockIdx.x * 256 + threadIdx.x;
    const int slice = CP_STRIDE / 4;
    const int b = idx / slice;
    const int i = idx - b * slice;
    const float4* base = p + (long)(b * CSPLIT) * slice + i;
    float4 s = make_float4(0.f, 0.f, 0.f, 0.f);
#pragma unroll
    for (int j = 0; j < CSPLIT; j++) {
        float4 v = base[(long)j * slice];
        s.x += v.x; s.y += v.y; s.z += v.z; s.w += v.w;
    }
    out[idx] = s;
}

// ---------------------------------------------------------------------------
// Additive scores (masked) -> g_sc. One block = (b, 8 queries, 256 enc range).
// grid (4, 32, 4). Warp w owns query q0+w; lane handles 4 e-rows per k tile.
// ---------------------------------------------------------------------------
__global__ __launch_bounds__(256) void score_kernel(
    const float* __restrict__ scale, const int* __restrict__ mask)
{
    extern __shared__ float sm[];
    float* qs  = sm;                  // 8 * 128
    float* scl = qs + 8 * kU;         // 128
    float* ks  = scl + kU;            // 128 * 132

    const int b   = blockIdx.z;
    const int q0  = blockIdx.y * 8;
    const int eh  = blockIdx.x * 256;
    const int tid = threadIdx.x;

#pragma unroll
    for (int i = 0; i < 4; i++)
        qs[tid + i * 256] = g_q[(b * kDEC + q0) * kU + tid + i * 256];
    if (tid < kU) scl[tid] = scale[tid];

    const int q    = tid >> 5;
    const int lane = tid & 31;
    const float* kbase = g_k + (long)b * kENC * kU;
    const int*   mrow  = mask + b * kENC;
    const float* qr = qs + q * kU;
    float* srow = g_sc + (long)(b * kDEC + q0 + q) * kENC;

    for (int et = eh; et < eh + 256; et += 128) {
        __syncthreads();
#pragma unroll
        for (int i = 0; i < 16; i++) {
            int f4  = tid + i * 256;
            int row = f4 >> 5;
            int col = (f4 & 31) * 4;
            *(float4*)(ks + row * 132 + col) =
                *(const float4*)(kbase + (long)(et + row) * kU + col);
        }
        __syncthreads();

        const float* k0 = ks + (lane +  0) * 132;
        const float* k1 = ks + (lane + 32) * 132;
        const float* k2 = ks + (lane + 64) * 132;
        const float* k3 = ks + (lane + 96) * 132;
        float s0 = 0.f, s1 = 0.f, s2 = 0.f, s3 = 0.f;
#pragma unroll
        for (int u = 0; u < kU; u += 4) {
            float4 qv = *(const float4*)(qr + u);
            float4 sv = *(const float4*)(scl + u);
            float4 a = *(const float4*)(k0 + u);
            float4 c = *(const float4*)(k1 + u);
            float4 d = *(const float4*)(k2 + u);
            float4 e = *(const float4*)(k3 + u);
            s0 = fmaf(sv.x, tanh_approx(qv.x + a.x), s0);
            s0 = fmaf(sv.y, tanh_approx(qv.y + a.y), s0);
            s0 = fmaf(sv.z, tanh_approx(qv.z + a.z), s0);
            s0 = fmaf(sv.w, tanh_approx(qv.w + a.w), s0);
            s1 = fmaf(sv.x, tanh_approx(qv.x + c.x), s1);
            s1 = fmaf(sv.y, tanh_approx(qv.y + c.y), s1);
            s1 = fmaf(sv.z, tanh_approx(qv.z + c.z), s1);
            s1 = fmaf(sv.w, tanh_approx(qv.w + c.w), s1);
            s2 = fmaf(sv.x, tanh_approx(qv.x + d.x), s2);
            s2 = fmaf(sv.y, tanh_approx(qv.y + d.y), s2);
            s2 = fmaf(sv.z, tanh_approx(qv.z + d.z), s2);
            s2 = fmaf(sv.w, tanh_approx(qv.w + d.w), s2);
            s3 = fmaf(sv.x, tanh_approx(qv.x + e.x), s3);
            s3 = fmaf(sv.y, tanh_approx(qv.y + e.y), s3);
            s3 = fmaf(sv.z, tanh_approx(qv.z + e.z), s3);
            s3 = fmaf(sv.w, tanh_approx(qv.w + e.w), s3);
        }
        int e0 = et + lane, e1 = e0 + 32, e2 = e0 + 64, e3 = e0 + 96;
        srow[e0] = (mrow[e0] == 0) ? -1e9f : s0;
        srow[e1] = (mrow[e1] == 0) ? -1e9f : s1;
        srow[e2] = (mrow[e2] == 0) ? -1e9f : s2;
        srow[e3] = (mrow[e3] == 0) ? -1e9f : s3;
    }
}

// ---------------------------------------------------------------------------
// Softmax over g_sc rows -> wts. Warp per row, float4, L2-hot input.
// ---------------------------------------------------------------------------
__global__ __launch_bounds__(256) void softmax_kernel(float* __restrict__ wts)
{
    const int r    = blockIdx.x * 8 + (threadIdx.x >> 5);
    const int lane = threadIdx.x & 31;
    const float4* row4 = (const float4*)(g_sc + (long)r * kENC);

    float4 v[8];
    float mx = -3.4e38f;
#pragma unroll
    for (int j = 0; j < 8; j++) {
        v[j] = row4[lane + j * 32];
        mx = fmaxf(mx, fmaxf(fmaxf(v[j].x, v[j].y), fmaxf(v[j].z, v[j].w)));
    }
#pragma unroll
    for (int off = 16; off > 0; off >>= 1)
        mx = fmaxf(mx, __shfl_xor_sync(0xffffffffu, mx, off));

    float ssum = 0.f;
#pragma unroll
    for (int j = 0; j < 8; j++) {
        v[j].x = __expf(v[j].x - mx); v[j].y = __expf(v[j].y - mx);
        v[j].z = __expf(v[j].z - mx); v[j].w = __expf(v[j].w - mx);
        ssum += v[j].x + v[j].y + v[j].z + v[j].w;
    }
#pragma unroll
    for (int off = 16; off > 0; off >>= 1)
        ssum += __shfl_xor_sync(0xffffffffu, ssum, off);
    const float inv = 1.0f / ssum;

    float4* w4 = (float4*)(wts + (long)r * kENC);
#pragma unroll
    for (int j = 0; j < 8; j++)
        w4[lane + j * 32] = make_float4(v[j].x * inv, v[j].y * inv,
                                        v[j].z * inv, v[j].w * inv);
}

// ---------------------------------------------------------------------------
extern "C" void kernel_launch(void* const* d_in, const int* in_sizes, int n_in,
                              void* d_out, int out_size)
{
    const float* query = (const float*)d_in[0];
    const float* value = (const float*)d_in[1];
    const int*   mask  = (const int*)d_in[2];
    const float* W1    = (const float*)d_in[3];
    const float* W2    = (const float*)d_in[4];
    const float* scale = (const float*)d_in[5];

    float* ctx = (float*)d_out;                          // (B, DEC, HID)
    float* wts = ctx + (size_t)kB * kDEC * kHID;         // (B, DEC, ENC)

    float* cp;
    cudaGetSymbolAddress((void**)&cp, g_cp);

    cudaFuncSetAttribute(score_kernel,
        cudaFuncAttributeMaxDynamicSharedMemorySize, SCORE_SMEM_BYTES);

    // combined q+k projections, balanced split (320 blocks)
    proj_kernel<<<320, 256>>>(query, W1, value, W2);

    // sum projection parts
    reduce_qk_kernel<<<(QN + KN) / 256, 256>>>();

    // masked scores (grid 512, 3 CTAs/SM)
    score_kernel<<<dim3(4, 32, kB), 256, SCORE_SMEM_BYTES>>>(scale, mask);

    // softmax -> weights
    softmax_kernel<<<kB * kDEC / 8, 256>>>(wts);

    // context: per-batch (256,1024)@(1024,512), split 8 -> 256 blocks
    gemm128<<<dim3(4, 2, kB * CSPLIT), 256>>>(wts, value, cp, 256, 512, 1024, CSPLIT,
                                              (long)kDEC * kENC, (long)kENC * kHID);

    // sum ctx parts -> d_out
    reduce_ctx_kernel<<<(kB * CP_STRIDE / 4) / 256, 256>>>((float4*)ctx);
}